// round 15
// baseline (speedup 1.0000x reference)
#include <cuda_runtime.h>
#include <cuda_fp16.h>
#include <math.h>
#include <stdint.h>

// Problem constants
#define BB 8
#define SS 1024
#define IN_DIM 3
#define DD 512
#define HH 8
#define FF 2048
#define LL 4
#define OUTD 6
#define DH 64
#define NT (BB*SS)   // 8192 tokens
#define QKVN 1536    // fused QKV output width

// ======================= PTX helpers (portable, sm_80+) ====================
__device__ __forceinline__ uint32_t smem_to_u32(const void* p) {
    uint32_t a;
    asm("{ .reg .u64 t; cvta.to.shared.u64 t, %1; cvt.u32.u64 %0, t; }" : "=r"(a) : "l"(p));
    return a;
}
#define CP_ASYNC16(dst, src) \
    asm volatile("cp.async.cg.shared.global [%0], [%1], 16;" :: "r"(dst), "l"(src))
#define CP_ASYNC4(dst, src) \
    asm volatile("cp.async.ca.shared.global [%0], [%1], 4;" :: "r"(dst), "l"(src))
#define CP_COMMIT() asm volatile("cp.async.commit_group;" ::: "memory")
#define CP_WAIT(n)  asm volatile("cp.async.wait_group %0;" :: "n"(n) : "memory")

__device__ __forceinline__ void ldm_x4(uint32_t* r, uint32_t addr) {
    asm volatile("ldmatrix.sync.aligned.m8n8.x4.shared.b16 {%0,%1,%2,%3}, [%4];"
        : "=r"(r[0]), "=r"(r[1]), "=r"(r[2]), "=r"(r[3]) : "r"(addr));
}
__device__ __forceinline__ void ldm_x4_t(uint32_t* r, uint32_t addr) {
    asm volatile("ldmatrix.sync.aligned.m8n8.x4.trans.shared.b16 {%0,%1,%2,%3}, [%4];"
        : "=r"(r[0]), "=r"(r[1]), "=r"(r[2]), "=r"(r[3]) : "r"(addr));
}
__device__ __forceinline__ void mma_f16(float* d, const uint32_t* a, const uint32_t* b) {
    asm volatile("mma.sync.aligned.m16n8k16.row.col.f32.f16.f16.f32 "
        "{%0,%1,%2,%3}, {%4,%5,%6,%7}, {%8,%9}, {%0,%1,%2,%3};"
        : "+f"(d[0]), "+f"(d[1]), "+f"(d[2]), "+f"(d[3])
        : "r"(a[0]), "r"(a[1]), "r"(a[2]), "r"(a[3]), "r"(b[0]), "r"(b[1]));
}

// ---------------- scratch (device globals; no allocation allowed) ----------
__device__ float g_h  [NT*DD];
__device__ float g_mask[NT];
__device__ float g_pool[BB*16*DD];
__device__ float g_cnt[BB*16];
// fp16 activations
__device__ __half g_hh  [NT*DD];
__device__ __half g_ao  [NT*DD];
__device__ __half g_fh  [NT*FF];
__device__ __half g_qkv [NT*QKVN];
// fp16, transposed weights [N, K]
__device__ __half g_wqkv[LL*QKVN*DD];
__device__ __half g_wo[LL*DD*DD];
__device__ __half g_w1[LL*FF*DD];
__device__ __half g_w2[LL*DD*FF];

__device__ __forceinline__ uint32_t packpair(float a, float b) {
    __half2 t = __floats2half2_rn(a, b);
    return *reinterpret_cast<uint32_t*>(&t);
}
__device__ __forceinline__ uint32_t hscale8(uint32_t x) {  // *0.125 exact (fp16)
    __half2 v = *reinterpret_cast<__half2*>(&x);
    __half2 s = __floats2half2_rn(0.125f, 0.125f);
    v = __hmul2(v, s);
    return *reinterpret_cast<uint32_t*>(&v);
}
__device__ __forceinline__ float wred_sum(float v) {
    #pragma unroll
    for (int o = 16; o > 0; o >>= 1) v += __shfl_xor_sync(0xffffffffu, v, o);
    return v;
}
__device__ __forceinline__ float block_sum(float v, float* red) {
    int lane = threadIdx.x & 31, w = threadIdx.x >> 5;
    v = wred_sum(v);
    if (lane == 0) red[w] = v;
    __syncthreads();
    if (w == 0) {
        float r = (lane < (int)(blockDim.x >> 5)) ? red[lane] : 0.f;
        r = wred_sum(r);
        if (lane == 0) red[32] = r;
    }
    __syncthreads();
    return red[32];
}

// -------- single-launch weight prep: transpose + fp16, QKV packed ---------
__global__ void wprep_all(const float* __restrict__ Wq, const float* __restrict__ Wk,
                          const float* __restrict__ Wv, const float* __restrict__ Wo,
                          const float* __restrict__ W1, const float* __restrict__ W2) {
    __shared__ float tile[32][33];
    int gid = blockIdx.x;
    int l = gid / 3072, r = gid % 3072;
    const float* src; __half* dh;
    int K, N, n0, k0;
    if (r < 1024) {
        int widx = r >> 8, t = r & 255;
        n0 = (t & 15) * 32; k0 = (t >> 4) * 32;
        K = DD; N = DD;
        size_t wo = (size_t)l * DD * DD;
        if (widx < 3) {
            const float* ws[3] = {Wq, Wk, Wv};
            src = ws[widx] + wo;
            dh = g_wqkv + (size_t)l * QKVN * DD + (size_t)widx * DD * DD;
        } else {
            src = Wo + wo; dh = g_wo + wo;
        }
    } else if (r < 2048) {
        int t = r - 1024;
        n0 = (t & 63) * 32; k0 = (t >> 6) * 32;
        K = DD; N = FF;
        size_t wo = (size_t)l * FF * DD;
        src = W1 + wo; dh = g_w1 + wo;
    } else {
        int t = r - 2048;
        n0 = (t & 15) * 32; k0 = (t >> 4) * 32;
        K = FF; N = DD;
        size_t wo = (size_t)l * DD * FF;
        src = W2 + wo; dh = g_w2 + wo;
    }
    int tx = threadIdx.x, ty = threadIdx.y;
    #pragma unroll
    for (int j = 0; j < 32; j += 8)
        tile[ty + j][tx] = src[(size_t)(k0 + ty + j) * N + n0 + tx];
    __syncthreads();
    #pragma unroll
    for (int j = 0; j < 32; j += 8) {
        size_t idx = (size_t)(n0 + ty + j) * K + k0 + tx;
        dh[idx] = __float2half(tile[tx][ty + j]);
    }
}

// ---------------- embed: h = x@Wproj + bproj + PE ; mask ----------------
__global__ void embed_kernel(const float* __restrict__ x,
                             const float* __restrict__ Wp,
                             const float* __restrict__ bp,
                             float* __restrict__ h,
                             float* __restrict__ maskf) {
    int t = blockIdx.x;
    int s = t & (SS - 1);
    const float* xt = x + (size_t)t * IN_DIM;
    float x0 = xt[0], x1 = xt[1], x2 = xt[2];
    if (threadIdx.x == 0)
        maskf[t] = ((fabsf(x0) + fabsf(x1) + fabsf(x2)) == 0.f) ? 0.f : 1.f;
    #pragma unroll
    for (int r = 0; r < 2; r++) {
        int d = threadIdx.x + r * 256;
        float val = x0 * Wp[d] + x1 * Wp[DD + d] + x2 * Wp[2*DD + d] + bp[d];
        float freq = expf(-(float)(d & ~1) * (9.210340371976184f / (float)DD));
        float ang = (float)s * freq;
        val += (d & 1) ? cosf(ang) : sinf(ang);
        h[(size_t)t * DD + d] = val;
    }
}

// ------- warp-per-row LN (input already summed in h); emits fp16 ----------
__global__ __launch_bounds__(256)
void ln_kernel(float* __restrict__ h,
               const float* __restrict__ g,
               const float* __restrict__ bta,
               __half* __restrict__ oh) {
    int w = threadIdx.x >> 5, lane = threadIdx.x & 31;
    size_t t = (size_t)blockIdx.x * 8 + w;
    float* hp = h + t * DD;
    float v[16];
    float s = 0.f;
    #pragma unroll
    for (int i = 0; i < 4; i++) {
        int c = i * 128 + lane * 4;
        float4 a = *reinterpret_cast<const float4*>(hp + c);
        v[i*4+0]=a.x; v[i*4+1]=a.y; v[i*4+2]=a.z; v[i*4+3]=a.w;
        s += a.x + a.y + a.z + a.w;
    }
    float mean = wred_sum(s) * (1.f / (float)DD);
    float vs = 0.f;
    #pragma unroll
    for (int i = 0; i < 16; i++) { v[i] -= mean; vs += v[i] * v[i]; }
    float rs = rsqrtf(wred_sum(vs) * (1.f / (float)DD) + 1e-5f);
    #pragma unroll
    for (int i = 0; i < 4; i++) {
        int c = i * 128 + lane * 4;
        float4 gg = *reinterpret_cast<const float4*>(g + c);
        float4 bb = *reinterpret_cast<const float4*>(bta + c);
        float y0 = v[i*4+0] * rs * gg.x + bb.x;
        float y1 = v[i*4+1] * rs * gg.y + bb.y;
        float y2 = v[i*4+2] * rs * gg.z + bb.z;
        float y3 = v[i*4+3] * rs * gg.w + bb.w;
        *reinterpret_cast<float4*>(hp + c) = make_float4(y0, y1, y2, y3);
        *reinterpret_cast<__half2*>(oh + t*DD + c)     = __floats2half2_rn(y0, y1);
        *reinterpret_cast<__half2*>(oh + t*DD + c + 2) = __floats2half2_rn(y2, y3);
    }
}

// =================== warp-MMA fp16 GEMM (single product) ===================
// CTA tile 128(M)x64(N), 256 threads, 8 warps of 32x32, BK=32,
// 3-stage cp.async pipeline, 1 barrier/chunk, 3 CTAs/SM (24 warps/SM).
// EPI 0: fp32 C.  EPI 1: silu -> fp16.  EPI 2: fp16.  EPI 3: fp32 C += acc.
#define SMEM_STRIDE 80
#define A_BYTES     10240          // 128 rows * 80
#define B_BYTES     5120           // 64 rows * 80
#define STAGE_BYTES (A_BYTES + B_BYTES)   // 15360
#define GEMM_SMEM   (3 * STAGE_BYTES)     // 46080

template <int EPI>
__global__ __launch_bounds__(256, 3)
void gemm_mma(const __half* __restrict__ A, const __half* __restrict__ B,
              float* __restrict__ C, __half* __restrict__ Ch,
              int M, int N, int K) {
    extern __shared__ char smem[];
    const int tid = threadIdx.x, lane = tid & 31, wid = tid >> 5;
    const int mBase = blockIdx.y * 128, nBase = blockIdx.x * 64;
    const int wm = wid & 3, wn = wid >> 2;   // warp tile: rows wm*32, cols wn*32
    uint32_t sbase = smem_to_u32(smem);

    float acc[2][4][4];
    #pragma unroll
    for (int i = 0; i < 2; i++)
        #pragma unroll
        for (int j = 0; j < 4; j++)
            #pragma unroll
            for (int e = 0; e < 4; e++) acc[i][j][e] = 0.f;

    const int nChunks = K >> 5;
    // A loader: 512 pieces, 2/thread (row = tid>>1, pieces (tid&1)*2, +1)
    const int arow = tid >> 1, ap = (tid & 1) * 2;
    // B loader: 256 pieces, 1/thread
    const int brow = tid >> 2, bp = tid & 3;

    const int aRow  = lane & 15;
    const int aHalf = lane >> 4;
    const int bN    = (lane & 7) | ((lane & 16) >> 1);
    const int bHalf = (lane >> 3) & 1;

#define PRELOAD(c, buf) do { \
    uint32_t _st = sbase + (buf) * STAGE_BYTES; \
    int _kc = (c) << 5; \
    const char* _ga = (const char*)(A + (size_t)(mBase + arow) * K + _kc); \
    uint32_t _da = _st + arow * SMEM_STRIDE; \
    CP_ASYNC16(_da + ap * 16,       _ga + ap * 16); \
    CP_ASYNC16(_da + (ap + 1) * 16, _ga + (ap + 1) * 16); \
    const char* _gb = (const char*)(B + (size_t)(nBase + brow) * K + _kc); \
    CP_ASYNC16(_st + A_BYTES + brow * SMEM_STRIDE + bp * 16, _gb + bp * 16); \
} while (0)

    PRELOAD(0, 0); CP_COMMIT();
    PRELOAD(1, 1); CP_COMMIT();

    int buf = 0;
    for (int c = 0; c < nChunks; c++) {
        if (c + 1 < nChunks) CP_WAIT(1); else CP_WAIT(0);
        __syncthreads();   // orders reuse of buffer (c+2)%3 (read at c-1)
        if (c + 2 < nChunks) {
            int nb = buf + 2; if (nb >= 3) nb -= 3;
            PRELOAD(c + 2, nb); CP_COMMIT();
        }

        uint32_t stg   = sbase + buf * STAGE_BYTES;
        uint32_t aBase = stg + (wm * 32) * SMEM_STRIDE;
        uint32_t bBase = stg + A_BYTES + (wn * 32) * SMEM_STRIDE;

        #pragma unroll
        for (int ks = 0; ks < 2; ks++) {
            int koff  = ks * 32 + aHalf * 16;
            int koffb = ks * 32 + bHalf * 16;
            uint32_t af[2][4], bf[2][4];
            #pragma unroll
            for (int mi = 0; mi < 2; mi++)
                ldm_x4(af[mi], aBase + (mi * 16 + aRow) * SMEM_STRIDE + koff);
            #pragma unroll
            for (int j = 0; j < 2; j++)
                ldm_x4(bf[j], bBase + (j * 16 + bN) * SMEM_STRIDE + koffb);

            #pragma unroll
            for (int mi = 0; mi < 2; mi++)
                #pragma unroll
                for (int j = 0; j < 2; j++) {
                    mma_f16(acc[mi][j*2],   af[mi], bf[j]);
                    mma_f16(acc[mi][j*2+1], af[mi], bf[j] + 2);
                }
        }
        buf++; if (buf >= 3) buf = 0;
    }

    int rowb = mBase + wm * 32 + (lane >> 2);
    int colb = nBase + wn * 32 + (lane & 3) * 2;
    #pragma unroll
    for (int mi = 0; mi < 2; mi++) {
        #pragma unroll
        for (int ns = 0; ns < 4; ns++) {
            int row = rowb + mi * 16;
            int col = colb + ns * 8;
            float c0 = acc[mi][ns][0], c1 = acc[mi][ns][1];
            float c2 = acc[mi][ns][2], c3 = acc[mi][ns][3];
            if (EPI == 0) {
                *reinterpret_cast<float2*>(C + (size_t)row * N + col)       = make_float2(c0, c1);
                *reinterpret_cast<float2*>(C + (size_t)(row + 8) * N + col) = make_float2(c2, c3);
            } else if (EPI == 3) {
                float2 o0 = *reinterpret_cast<float2*>(C + (size_t)row * N + col);
                float2 o1 = *reinterpret_cast<float2*>(C + (size_t)(row + 8) * N + col);
                *reinterpret_cast<float2*>(C + (size_t)row * N + col)       = make_float2(o0.x + c0, o0.y + c1);
                *reinterpret_cast<float2*>(C + (size_t)(row + 8) * N + col) = make_float2(o1.x + c2, o1.y + c3);
            } else {
                if (EPI == 1) {
                    c0 = c0 / (1.f + __expf(-c0)); c1 = c1 / (1.f + __expf(-c1));
                    c2 = c2 / (1.f + __expf(-c2)); c3 = c3 / (1.f + __expf(-c3));
                }
                *reinterpret_cast<__half2*>(Ch + (size_t)row * N + col)       = __floats2half2_rn(c0, c1);
                *reinterpret_cast<__half2*>(Ch + (size_t)(row + 8) * N + col) = __floats2half2_rn(c2, c3);
            }
        }
    }
#undef PRELOAD
}

// =================== tensor-core flash attention (fp16) ====================
// BQ=128 per CTA (256 threads, 8 warps x 16 q-rows).
// Single-product QK and PV; 2-stage KV pipeline, one barrier per tile.
#define AST   144
#define AQBYTES (128*AST)                // 18432
#define AKV0  AQBYTES
#define AKVSZ (2*64*AST)                 // 18432 (Kh + Vh)
#define AMSK  (AKV0 + 2*AKVSZ)           // 55296
#define ATT_SMEM (AMSK + 2*256 + 256)

__global__ __launch_bounds__(256)
void attn_mma(const __half* __restrict__ qkv,
              const float* __restrict__ maskf,
              __half* __restrict__ outh) {
    extern __shared__ char smA[];
    uint32_t sb = smem_to_u32(smA);
    const int tid = threadIdx.x, lane = tid & 31, wid = tid >> 5;
    const int qt = blockIdx.x, hd = blockIdx.y, b = blockIdx.z;
    const size_t qtok0 = (size_t)b * SS + qt * 128;
    const size_t ktok0 = (size_t)b * SS;
    const int colbase = hd * DH;

    const __half* qh = qkv + colbase;
    const __half* kh = qkv + DD + colbase;
    const __half* vh = qkv + 2*DD + colbase;

    const int aRow = lane & 15, aHalf = lane >> 4;
    const int bN = (lane & 7) | ((lane & 16) >> 1), bHalf = (lane >> 3) & 1;
    const int vKey = (lane & 7) + ((lane >> 4) << 3), vCol = lane & 8;

    const int krow = tid >> 2, kp = (tid & 3) * 2;

#define KV_PRELOAD(kt, bufb) do { \
    size_t _tok = ktok0 + (size_t)(kt) * 64 + krow; \
    uint32_t _dst = sb + AKV0 + (bufb) * AKVSZ + krow * AST + kp * 16; \
    const char* _s0 = (const char*)(kh + _tok * QKVN) + kp * 16; \
    const char* _s1 = (const char*)(vh + _tok * QKVN) + kp * 16; \
    CP_ASYNC16(_dst + 0,            _s0); \
    CP_ASYNC16(_dst + 16,           _s0 + 16); \
    CP_ASYNC16(_dst + 64*AST + 0,   _s1); \
    CP_ASYNC16(_dst + 64*AST + 16,  _s1 + 16); \
    if (tid < 64) CP_ASYNC4(sb + AMSK + (bufb)*256 + tid*4, maskf + b*SS + (kt)*64 + tid); \
} while (0)

    {
        int qrow = tid >> 1, qp = (tid & 1) * 4;
        const char* gq = (const char*)(qh + (qtok0 + qrow) * QKVN) + qp * 16;
        uint32_t d = sb + qrow * AST + qp * 16;
        #pragma unroll
        for (int i = 0; i < 4; i++)
            CP_ASYNC16(d + i*16, gq + i*16);
    }
    KV_PRELOAD(0, 0);
    CP_COMMIT();

    uint32_t qhf[4][4];
    float oacc[8][4];
    #pragma unroll
    for (int i = 0; i < 8; i++)
        #pragma unroll
        for (int e = 0; e < 4; e++) oacc[i][e] = 0.f;
    float m0 = -1e30f, m1 = -1e30f, l0 = 0.f, l1 = 0.f;

    const int nTiles = SS / 64;
    for (int t = 0; t < nTiles; t++) {
        int buf = t & 1;
        CP_WAIT(0);
        __syncthreads();
        if (t + 1 < nTiles) { KV_PRELOAD(t + 1, (t + 1) & 1); CP_COMMIT(); }

        if (t == 0) {
            #pragma unroll
            for (int kc = 0; kc < 4; kc++) {
                uint32_t off = (wid * 16 + aRow) * AST + kc * 32 + aHalf * 16;
                ldm_x4(qhf[kc], sb + off);
                #pragma unroll
                for (int r = 0; r < 4; r++)
                    qhf[kc][r] = hscale8(qhf[kc][r]);
            }
        }

        uint32_t kvb = sb + AKV0 + buf * AKVSZ;
        float sacc[8][4];
        #pragma unroll
        for (int i = 0; i < 8; i++)
            #pragma unroll
            for (int e = 0; e < 4; e++) sacc[i][e] = 0.f;

        #pragma unroll
        for (int kc = 0; kc < 4; kc++) {
            uint32_t kf[4][4];
            #pragma unroll
            for (int nt4 = 0; nt4 < 4; nt4++) {
                uint32_t kb = kvb + (nt4 * 16 + bN) * AST + kc * 32 + bHalf * 16;
                ldm_x4(kf[nt4], kb);
            }
            #pragma unroll
            for (int nt4 = 0; nt4 < 4; nt4++) {
                mma_f16(sacc[nt4*2],   qhf[kc], kf[nt4]);
                mma_f16(sacc[nt4*2+1], qhf[kc], kf[nt4] + 2);
            }
        }

        const float* smk = (const float*)(smA + AMSK + buf * 256);
        float mx0 = -1e30f, mx1 = -1e30f;
        #pragma unroll
        for (int nt = 0; nt < 8; nt++) {
            float mk0 = smk[nt * 8 + (lane & 3) * 2];
            float mk1 = smk[nt * 8 + (lane & 3) * 2 + 1];
            if (mk0 == 0.f) { sacc[nt][0] = -1e30f; sacc[nt][2] = -1e30f; }
            if (mk1 == 0.f) { sacc[nt][1] = -1e30f; sacc[nt][3] = -1e30f; }
            mx0 = fmaxf(mx0, fmaxf(sacc[nt][0], sacc[nt][1]));
            mx1 = fmaxf(mx1, fmaxf(sacc[nt][2], sacc[nt][3]));
        }
        mx0 = fmaxf(mx0, __shfl_xor_sync(0xffffffffu, mx0, 1));
        mx0 = fmaxf(mx0, __shfl_xor_sync(0xffffffffu, mx0, 2));
        mx1 = fmaxf(mx1, __shfl_xor_sync(0xffffffffu, mx1, 1));
        mx1 = fmaxf(mx1, __shfl_xor_sync(0xffffffffu, mx1, 2));
        float mn0 = fmaxf(m0, mx0), mn1 = fmaxf(m1, mx1);
        float al0 = __expf(m0 - mn0), al1 = __expf(m1 - mn1);
        m0 = mn0; m1 = mn1;
        float ps0 = 0.f, ps1 = 0.f;
        #pragma unroll
        for (int nt = 0; nt < 8; nt++) {
            sacc[nt][0] = __expf(sacc[nt][0] - mn0);
            sacc[nt][1] = __expf(sacc[nt][1] - mn0);
            sacc[nt][2] = __expf(sacc[nt][2] - mn1);
            sacc[nt][3] = __expf(sacc[nt][3] - mn1);
            ps0 += sacc[nt][0] + sacc[nt][1];
            ps1 += sacc[nt][2] + sacc[nt][3];
        }
        l0 = l0 * al0 + ps0;
        l1 = l1 * al1 + ps1;
        #pragma unroll
        for (int nt = 0; nt < 8; nt++) {
            oacc[nt][0] *= al0; oacc[nt][1] *= al0;
            oacc[nt][2] *= al1; oacc[nt][3] *= al1;
        }

        #pragma unroll
        for (int kc2 = 0; kc2 < 4; kc2++) {
            uint32_t pf[4];
            pf[0] = packpair(sacc[2*kc2][0],   sacc[2*kc2][1]);
            pf[1] = packpair(sacc[2*kc2][2],   sacc[2*kc2][3]);
            pf[2] = packpair(sacc[2*kc2+1][0], sacc[2*kc2+1][1]);
            pf[3] = packpair(sacc[2*kc2+1][2], sacc[2*kc2+1][3]);
            uint32_t vf[4][4];
            #pragma unroll
            for (int nt4 = 0; nt4 < 4; nt4++) {
                uint32_t va = kvb + 64*AST + (kc2*16 + vKey)*AST + (nt4*16 + vCol)*2;
                ldm_x4_t(vf[nt4], va);
            }
            #pragma unroll
            for (int nt4 = 0; nt4 < 4; nt4++) {
                uint32_t b0[2] = {vf[nt4][0], vf[nt4][2]}, b1[2] = {vf[nt4][1], vf[nt4][3]};
                mma_f16(oacc[nt4*2],   pf, b0);
                mma_f16(oacc[nt4*2+1], pf, b1);
            }
        }
    }

    l0 += __shfl_xor_sync(0xffffffffu, l0, 1);
    l0 += __shfl_xor_sync(0xffffffffu, l0, 2);
    l1 += __shfl_xor_sync(0xffffffffu, l1, 1);
    l1 += __shfl_xor_sync(0xffffffffu, l1, 2);
    float inv0 = 1.f / l0, inv1 = 1.f / l1;
    size_t tok0 = qtok0 + wid * 16 + (lane >> 2);
    size_t tok1 = tok0 + 8;
    int cb = colbase + (lane & 3) * 2;
    #pragma unroll
    for (int nt = 0; nt < 8; nt++) {
        int col = cb + nt * 8;
        *reinterpret_cast<__half2*>(outh + tok0*DD + col) =
            __floats2half2_rn(oacc[nt][0] * inv0, oacc[nt][1] * inv0);
        *reinterpret_cast<__half2*>(outh + tok1*DD + col) =
            __floats2half2_rn(oacc[nt][2] * inv1, oacc[nt][3] * inv1);
    }
#undef KV_PRELOAD
}

// ---------------- pooling: deterministic two-stage ------------------------
__global__ void pool_partial(const float* __restrict__ h,
                             const float* __restrict__ maskf) {
    __shared__ float scnt[64];
    int b = blockIdx.x, chunk = blockIdx.y, tid = threadIdx.x;
    int s0 = chunk * 64;
    if (tid < 64) scnt[tid] = maskf[b * SS + s0 + tid];
    float a0 = 0.f, a1 = 0.f;
    for (int s = s0; s < s0 + 64; s++) {
        float np = maskf[b * SS + s];
        const float* hp = h + (size_t)(b * SS + s) * DD;
        a0 += hp[tid] * np;
        a1 += hp[tid + 256] * np;
    }
    g_pool[(size_t)(b * 16 + chunk) * DD + tid]       = a0;
    g_pool[(size_t)(b * 16 + chunk) * DD + tid + 256] = a1;
    __syncthreads();
    if (tid == 0) {
        float c = 0.f;
        #pragma unroll
        for (int i = 0; i < 64; i++) c += scnt[i];
        g_cnt[b * 16 + chunk] = c;
    }
}

__global__ void pool_final(const float* __restrict__ Wout,
                           const float* __restrict__ bout,
                           float* __restrict__ out) {
    __shared__ float red[40];
    int b = blockIdx.x, tid = threadIdx.x;
    float a0 = 0.f, a1 = 0.f, cnt = 0.f;
    #pragma unroll
    for (int c = 0; c < 16; c++) {
        a0 += g_pool[(size_t)(b * 16 + c) * DD + tid];
        a1 += g_pool[(size_t)(b * 16 + c) * DD + tid + 256];
        cnt += g_cnt[b * 16 + c];
    }
    float inv = 1.f / (cnt + 1e-8f);
    float p0 = a0 * inv, p1 = a1 * inv;
    for (int j = 0; j < OUTD; j++) {
        float p = p0 * Wout[tid * OUTD + j] + p1 * Wout[(tid + 256) * OUTD + j];
        float ssum = block_sum(p, red);
        if (tid == 0) out[b * OUTD + j] = ssum + bout[j];
    }
}

// ---------------- launch ---------------------------------------------------
extern "C" void kernel_launch(void* const* d_in, const int* in_sizes, int n_in,
                              void* d_out, int out_size) {
    const float* x     = (const float*)d_in[0];
    const float* Wproj = (const float*)d_in[1];
    const float* bproj = (const float*)d_in[2];
    const float* gp    = (const float*)d_in[3];
    const float* bp    = (const float*)d_in[4];
    const float* Wq    = (const float*)d_in[5];
    const float* Wk    = (const float*)d_in[6];
    const float* Wv    = (const float*)d_in[7];
    const float* Wo    = (const float*)d_in[8];
    const float* g1    = (const float*)d_in[9];
    const float* b1    = (const float*)d_in[10];
    const float* W1    = (const float*)d_in[11];
    const float* W2    = (const float*)d_in[12];
    const float* g2    = (const float*)d_in[13];
    const float* b2    = (const float*)d_in[14];
    const float* gf    = (const float*)d_in[15];
    const float* bf    = (const float*)d_in[16];
    const float* Wout  = (const float*)d_in[17];
    const float* bout  = (const float*)d_in[18];

    float *h, *mask;
    cudaGetSymbolAddress((void**)&h,    g_h);
    cudaGetSymbolAddress((void**)&mask, g_mask);
    __half *hh, *ao, *fh, *qkv;
    cudaGetSymbolAddress((void**)&hh,  g_hh);
    cudaGetSymbolAddress((void**)&ao,  g_ao);
    cudaGetSymbolAddress((void**)&fh,  g_fh);
    cudaGetSymbolAddress((void**)&qkv, g_qkv);
    __half *wqkv, *wo, *w1, *w2;
    cudaGetSymbolAddress((void**)&wqkv, g_wqkv);
    cudaGetSymbolAddress((void**)&wo,   g_wo);
    cudaGetSymbolAddress((void**)&w1,   g_w1);
    cudaGetSymbolAddress((void**)&w2,   g_w2);

    cudaFuncSetAttribute(gemm_mma<1>, cudaFuncAttributeMaxDynamicSharedMemorySize, GEMM_SMEM);
    cudaFuncSetAttribute(gemm_mma<2>, cudaFuncAttributeMaxDynamicSharedMemorySize, GEMM_SMEM);
    cudaFuncSetAttribute(gemm_mma<3>, cudaFuncAttributeMaxDynamicSharedMemorySize, GEMM_SMEM);
    cudaFuncSetAttribute(attn_mma,    cudaFuncAttributeMaxDynamicSharedMemorySize, ATT_SMEM);

    wprep_all<<<12288, dim3(32, 8)>>>(Wq, Wk, Wv, Wo, W1, W2);

    embed_kernel<<<NT, 256>>>(x, Wproj, bproj, h, mask);
    ln_kernel<<<NT/8, 256>>>(h, gp, bp, hh);

    dim3 gQKV(QKVN / 64, NT / 128);
    dim3 gO(DD / 64, NT / 128);
    dim3 gF1(FF / 64, NT / 128);
    dim3 gAttn(SS / 128, HH, BB);

    for (int l = 0; l < LL; l++) {
        size_t oqkv = (size_t)l * QKVN * DD;
        size_t od = (size_t)l * DD * DD, of1 = (size_t)l * FF * DD, of2 = (size_t)l * DD * FF;
        gemm_mma<2><<<gQKV, 256, GEMM_SMEM>>>(hh, wqkv + oqkv, nullptr, qkv, NT, QKVN, DD);
        attn_mma<<<gAttn, 256, ATT_SMEM>>>(qkv, mask, ao);
        gemm_mma<3><<<gO, 256, GEMM_SMEM>>>(ao, wo + od, h, nullptr, NT, DD, DD);
        ln_kernel<<<NT/8, 256>>>(h, g1 + l * DD, b1 + l * DD, hh);
        gemm_mma<1><<<gF1, 256, GEMM_SMEM>>>(hh, w1 + of1, nullptr, fh, NT, FF, DD);
        gemm_mma<3><<<gO, 256, GEMM_SMEM>>>(fh, w2 + of2, h, nullptr, NT, DD, FF);
        ln_kernel<<<NT/8, 256>>>(h, g2 + l * DD, b2 + l * DD, hh);
    }

    ln_kernel<<<NT/8, 256>>>(h, gf, bf, hh);
    pool_partial<<<dim3(BB, 16), 256>>>(h, mask);
    pool_final<<<BB, 256>>>(Wout, bout, (float*)d_out);
}

// round 16
// speedup vs baseline: 1.0324x; 1.0324x over previous
#include <cuda_runtime.h>
#include <cuda_fp16.h>
#include <math.h>
#include <stdint.h>

// Problem constants
#define BB 8
#define SS 1024
#define IN_DIM 3
#define DD 512
#define HH 8
#define FF 2048
#define LL 4
#define OUTD 6
#define DH 64
#define NT (BB*SS)   // 8192 tokens
#define QKVN 1536    // fused QKV output width

// ======================= PTX helpers (portable, sm_80+) ====================
__device__ __forceinline__ uint32_t smem_to_u32(const void* p) {
    uint32_t a;
    asm("{ .reg .u64 t; cvta.to.shared.u64 t, %1; cvt.u32.u64 %0, t; }" : "=r"(a) : "l"(p));
    return a;
}
#define CP_ASYNC16(dst, src) \
    asm volatile("cp.async.cg.shared.global [%0], [%1], 16;" :: "r"(dst), "l"(src))
#define CP_ASYNC4(dst, src) \
    asm volatile("cp.async.ca.shared.global [%0], [%1], 4;" :: "r"(dst), "l"(src))
#define CP_COMMIT() asm volatile("cp.async.commit_group;" ::: "memory")
#define CP_WAIT(n)  asm volatile("cp.async.wait_group %0;" :: "n"(n) : "memory")

__device__ __forceinline__ void ldm_x4(uint32_t* r, uint32_t addr) {
    asm volatile("ldmatrix.sync.aligned.m8n8.x4.shared.b16 {%0,%1,%2,%3}, [%4];"
        : "=r"(r[0]), "=r"(r[1]), "=r"(r[2]), "=r"(r[3]) : "r"(addr));
}
__device__ __forceinline__ void ldm_x4_t(uint32_t* r, uint32_t addr) {
    asm volatile("ldmatrix.sync.aligned.m8n8.x4.trans.shared.b16 {%0,%1,%2,%3}, [%4];"
        : "=r"(r[0]), "=r"(r[1]), "=r"(r[2]), "=r"(r[3]) : "r"(addr));
}
__device__ __forceinline__ void mma_f16(float* d, const uint32_t* a, const uint32_t* b) {
    asm volatile("mma.sync.aligned.m16n8k16.row.col.f32.f16.f16.f32 "
        "{%0,%1,%2,%3}, {%4,%5,%6,%7}, {%8,%9}, {%0,%1,%2,%3};"
        : "+f"(d[0]), "+f"(d[1]), "+f"(d[2]), "+f"(d[3])
        : "r"(a[0]), "r"(a[1]), "r"(a[2]), "r"(a[3]), "r"(b[0]), "r"(b[1]));
}

// ---------------- scratch (device globals; no allocation allowed) ----------
__device__ float g_h  [NT*DD];
__device__ float g_mask[NT];
__device__ float g_pool[BB*16*DD];
__device__ float g_cnt[BB*16];
// fp16 activations
__device__ __half g_hh  [NT*DD];
__device__ __half g_ao  [NT*DD];
__device__ __half g_fh  [NT*FF];
__device__ __half g_qkv [NT*QKVN];
// fp16, transposed weights [N, K]  (Wq block pre-scaled by 0.125)
__device__ __half g_wqkv[LL*QKVN*DD];
__device__ __half g_wo[LL*DD*DD];
__device__ __half g_w1[LL*FF*DD];
__device__ __half g_w2[LL*DD*FF];

__device__ __forceinline__ uint32_t packpair(float a, float b) {
    __half2 t = __floats2half2_rn(a, b);
    return *reinterpret_cast<uint32_t*>(&t);
}
__device__ __forceinline__ float wred_sum(float v) {
    #pragma unroll
    for (int o = 16; o > 0; o >>= 1) v += __shfl_xor_sync(0xffffffffu, v, o);
    return v;
}
__device__ __forceinline__ float block_sum(float v, float* red) {
    int lane = threadIdx.x & 31, w = threadIdx.x >> 5;
    v = wred_sum(v);
    if (lane == 0) red[w] = v;
    __syncthreads();
    if (w == 0) {
        float r = (lane < (int)(blockDim.x >> 5)) ? red[lane] : 0.f;
        r = wred_sum(r);
        if (lane == 0) red[32] = r;
    }
    __syncthreads();
    return red[32];
}

// -------- single-launch weight prep: transpose + fp16, QKV packed ---------
// Wq is pre-scaled by 0.125 (exact power-of-2) so attention skips Q scaling.
__global__ void wprep_all(const float* __restrict__ Wq, const float* __restrict__ Wk,
                          const float* __restrict__ Wv, const float* __restrict__ Wo,
                          const float* __restrict__ W1, const float* __restrict__ W2) {
    __shared__ float tile[32][33];
    int gid = blockIdx.x;
    int l = gid / 3072, r = gid % 3072;
    const float* src; __half* dh;
    int K, N, n0, k0;
    float scale = 1.f;
    if (r < 1024) {
        int widx = r >> 8, t = r & 255;
        n0 = (t & 15) * 32; k0 = (t >> 4) * 32;
        K = DD; N = DD;
        size_t wo = (size_t)l * DD * DD;
        if (widx < 3) {
            const float* ws[3] = {Wq, Wk, Wv};
            src = ws[widx] + wo;
            dh = g_wqkv + (size_t)l * QKVN * DD + (size_t)widx * DD * DD;
            if (widx == 0) scale = 0.125f;   // fold softmax scale into Wq
        } else {
            src = Wo + wo; dh = g_wo + wo;
        }
    } else if (r < 2048) {
        int t = r - 1024;
        n0 = (t & 63) * 32; k0 = (t >> 6) * 32;
        K = DD; N = FF;
        size_t wo = (size_t)l * FF * DD;
        src = W1 + wo; dh = g_w1 + wo;
    } else {
        int t = r - 2048;
        n0 = (t & 15) * 32; k0 = (t >> 4) * 32;
        K = FF; N = DD;
        size_t wo = (size_t)l * DD * FF;
        src = W2 + wo; dh = g_w2 + wo;
    }
    int tx = threadIdx.x, ty = threadIdx.y;
    #pragma unroll
    for (int j = 0; j < 32; j += 8)
        tile[ty + j][tx] = src[(size_t)(k0 + ty + j) * N + n0 + tx];
    __syncthreads();
    #pragma unroll
    for (int j = 0; j < 32; j += 8) {
        size_t idx = (size_t)(n0 + ty + j) * K + k0 + tx;
        dh[idx] = __float2half(tile[tx][ty + j] * scale);
    }
}

// ---------------- embed: h = x@Wproj + bproj + PE ; mask ----------------
__global__ void embed_kernel(const float* __restrict__ x,
                             const float* __restrict__ Wp,
                             const float* __restrict__ bp,
                             float* __restrict__ h,
                             float* __restrict__ maskf) {
    int t = blockIdx.x;
    int s = t & (SS - 1);
    const float* xt = x + (size_t)t * IN_DIM;
    float x0 = xt[0], x1 = xt[1], x2 = xt[2];
    if (threadIdx.x == 0)
        maskf[t] = ((fabsf(x0) + fabsf(x1) + fabsf(x2)) == 0.f) ? 0.f : 1.f;
    #pragma unroll
    for (int r = 0; r < 2; r++) {
        int d = threadIdx.x + r * 256;
        float val = x0 * Wp[d] + x1 * Wp[DD + d] + x2 * Wp[2*DD + d] + bp[d];
        float freq = expf(-(float)(d & ~1) * (9.210340371976184f / (float)DD));
        float ang = (float)s * freq;
        val += (d & 1) ? cosf(ang) : sinf(ang);
        h[(size_t)t * DD + d] = val;
    }
}

// ------- warp-per-row LN; emits fp16 unless oh == nullptr -----------------
__global__ __launch_bounds__(256)
void ln_kernel(float* __restrict__ h,
               const float* __restrict__ g,
               const float* __restrict__ bta,
               __half* __restrict__ oh) {
    int w = threadIdx.x >> 5, lane = threadIdx.x & 31;
    size_t t = (size_t)blockIdx.x * 8 + w;
    float* hp = h + t * DD;
    float v[16];
    float s = 0.f;
    #pragma unroll
    for (int i = 0; i < 4; i++) {
        int c = i * 128 + lane * 4;
        float4 a = *reinterpret_cast<const float4*>(hp + c);
        v[i*4+0]=a.x; v[i*4+1]=a.y; v[i*4+2]=a.z; v[i*4+3]=a.w;
        s += a.x + a.y + a.z + a.w;
    }
    float mean = wred_sum(s) * (1.f / (float)DD);
    float vs = 0.f;
    #pragma unroll
    for (int i = 0; i < 16; i++) { v[i] -= mean; vs += v[i] * v[i]; }
    float rs = rsqrtf(wred_sum(vs) * (1.f / (float)DD) + 1e-5f);
    #pragma unroll
    for (int i = 0; i < 4; i++) {
        int c = i * 128 + lane * 4;
        float4 gg = *reinterpret_cast<const float4*>(g + c);
        float4 bb = *reinterpret_cast<const float4*>(bta + c);
        float y0 = v[i*4+0] * rs * gg.x + bb.x;
        float y1 = v[i*4+1] * rs * gg.y + bb.y;
        float y2 = v[i*4+2] * rs * gg.z + bb.z;
        float y3 = v[i*4+3] * rs * gg.w + bb.w;
        *reinterpret_cast<float4*>(hp + c) = make_float4(y0, y1, y2, y3);
        if (oh) {
            *reinterpret_cast<__half2*>(oh + t*DD + c)     = __floats2half2_rn(y0, y1);
            *reinterpret_cast<__half2*>(oh + t*DD + c + 2) = __floats2half2_rn(y2, y3);
        }
    }
}

// =================== warp-MMA fp16 GEMM (single product) ===================
// 128x128 CTA, 8 warps of 32x64, BK=32, 3-stage pipeline, 1 barrier/chunk.
// EPI 0: fp32 C.  EPI 1: silu -> fp16.  EPI 2: fp16.  EPI 3: fp32 C += acc.
#define SMEM_STRIDE 80
#define MAT_BYTES   10240
#define GEMM_SMEM   (3 * 2 * MAT_BYTES)   // 61440

template <int EPI>
__global__ __launch_bounds__(256, 2)
void gemm_mma(const __half* __restrict__ A, const __half* __restrict__ B,
              float* __restrict__ C, __half* __restrict__ Ch,
              int M, int N, int K) {
    extern __shared__ char smem[];
    const int tid = threadIdx.x, lane = tid & 31, wid = tid >> 5;
    const int mBase = blockIdx.y * 128, nBase = blockIdx.x * 128;
    const int wm = wid >> 1, wn = wid & 1;
    uint32_t sbase = smem_to_u32(smem);

    float acc[2][8][4];
    #pragma unroll
    for (int i = 0; i < 2; i++)
        #pragma unroll
        for (int j = 0; j < 8; j++)
            #pragma unroll
            for (int e = 0; e < 4; e++) acc[i][j][e] = 0.f;

    const int nChunks = K >> 5;
    int idx0 = tid << 1;
    int r0 = idx0 >> 2, p0 = idx0 & 3;
    int p1 = p0 + 1;

    int aRow  = lane & 15;
    int aHalf = lane >> 4;
    int bN    = (lane & 7) | ((lane & 16) >> 1);
    int bHalf = (lane >> 3) & 1;

    const __half* gmat[2] = {A, B};
    int rbase[2] = {mBase, nBase};

#define PRELOAD(c, buf) do { \
    uint32_t _dst = sbase + (buf) * (2 * MAT_BYTES); \
    int _kc = (c) << 5; \
    _Pragma("unroll") \
    for (int _m = 0; _m < 2; _m++) { \
        const char* _g = (const char*)(gmat[_m] + (size_t)(rbase[_m] + r0) * K + _kc); \
        uint32_t _d = _dst + _m * MAT_BYTES + r0 * SMEM_STRIDE; \
        CP_ASYNC16(_d + p0 * 16, _g + p0 * 16); \
        CP_ASYNC16(_d + p1 * 16, _g + p1 * 16); \
    } \
} while (0)

    PRELOAD(0, 0); CP_COMMIT();
    PRELOAD(1, 1); CP_COMMIT();

    int buf = 0;
    for (int c = 0; c < nChunks; c++) {
        if (c + 1 < nChunks) CP_WAIT(1); else CP_WAIT(0);
        __syncthreads();
        if (c + 2 < nChunks) {
            int nb = buf + 2; if (nb >= 3) nb -= 3;
            PRELOAD(c + 2, nb); CP_COMMIT();
        }

        uint32_t bufb  = sbase + buf * (2 * MAT_BYTES);
        uint32_t aBase = bufb + (wm * 32) * SMEM_STRIDE;
        uint32_t bBase = bufb + MAT_BYTES + (wn * 64) * SMEM_STRIDE;

        #pragma unroll
        for (int ks = 0; ks < 2; ks++) {
            int koff  = ks * 32 + aHalf * 16;
            int koffb = ks * 32 + bHalf * 16;
            uint32_t af[2][4], bf[4][4];
            #pragma unroll
            for (int mi = 0; mi < 2; mi++)
                ldm_x4(af[mi], aBase + (mi * 16 + aRow) * SMEM_STRIDE + koff);
            #pragma unroll
            for (int g = 0; g < 4; g++)
                ldm_x4(bf[g], bBase + (g * 16 + bN) * SMEM_STRIDE + koffb);

            #pragma unroll
            for (int mi = 0; mi < 2; mi++)
                #pragma unroll
                for (int g = 0; g < 4; g++) {
                    mma_f16(acc[mi][g*2],   af[mi], bf[g]);
                    mma_f16(acc[mi][g*2+1], af[mi], bf[g] + 2);
                }
        }
        buf++; if (buf >= 3) buf = 0;
    }

    int rowb = mBase + wm * 32 + (lane >> 2);
    int colb = nBase + wn * 64 + (lane & 3) * 2;
    #pragma unroll
    for (int mi = 0; mi < 2; mi++) {
        #pragma unroll
        for (int ns = 0; ns < 8; ns++) {
            int row = rowb + mi * 16;
            int col = colb + ns * 8;
            float c0 = acc[mi][ns][0], c1 = acc[mi][ns][1];
            float c2 = acc[mi][ns][2], c3 = acc[mi][ns][3];
            if (EPI == 0) {
                *reinterpret_cast<float2*>(C + (size_t)row * N + col)       = make_float2(c0, c1);
                *reinterpret_cast<float2*>(C + (size_t)(row + 8) * N + col) = make_float2(c2, c3);
            } else if (EPI == 3) {
                float2 o0 = *reinterpret_cast<float2*>(C + (size_t)row * N + col);
                float2 o1 = *reinterpret_cast<float2*>(C + (size_t)(row + 8) * N + col);
                *reinterpret_cast<float2*>(C + (size_t)row * N + col)       = make_float2(o0.x + c0, o0.y + c1);
                *reinterpret_cast<float2*>(C + (size_t)(row + 8) * N + col) = make_float2(o1.x + c2, o1.y + c3);
            } else {
                if (EPI == 1) {
                    c0 = c0 / (1.f + __expf(-c0)); c1 = c1 / (1.f + __expf(-c1));
                    c2 = c2 / (1.f + __expf(-c2)); c3 = c3 / (1.f + __expf(-c3));
                }
                *reinterpret_cast<__half2*>(Ch + (size_t)row * N + col)       = __floats2half2_rn(c0, c1);
                *reinterpret_cast<__half2*>(Ch + (size_t)(row + 8) * N + col) = __floats2half2_rn(c2, c3);
            }
        }
    }
#undef PRELOAD
}

// =================== tensor-core flash attention (fp16) ====================
// BQ=128 per CTA (256 threads, 8 warps x 16 q-rows). Q pre-scaled via Wq.
// Single-product QK and PV; 2-stage KV pipeline, one barrier per tile.
#define AST   144
#define AQBYTES (128*AST)                // 18432
#define AKV0  AQBYTES
#define AKVSZ (2*64*AST)                 // 18432 (Kh + Vh)
#define AMSK  (AKV0 + 2*AKVSZ)           // 55296
#define ATT_SMEM (AMSK + 2*256 + 256)

__global__ __launch_bounds__(256)
void attn_mma(const __half* __restrict__ qkv,
              const float* __restrict__ maskf,
              __half* __restrict__ outh) {
    extern __shared__ char smA[];
    uint32_t sb = smem_to_u32(smA);
    const int tid = threadIdx.x, lane = tid & 31, wid = tid >> 5;
    const int qt = blockIdx.x, hd = blockIdx.y, b = blockIdx.z;
    const size_t qtok0 = (size_t)b * SS + qt * 128;
    const size_t ktok0 = (size_t)b * SS;
    const int colbase = hd * DH;

    const __half* qh = qkv + colbase;
    const __half* kh = qkv + DD + colbase;
    const __half* vh = qkv + 2*DD + colbase;

    const int aRow = lane & 15, aHalf = lane >> 4;
    const int bN = (lane & 7) | ((lane & 16) >> 1), bHalf = (lane >> 3) & 1;
    const int vKey = (lane & 7) + ((lane >> 4) << 3), vCol = lane & 8;

    const int krow = tid >> 2, kp = (tid & 3) * 2;

#define KV_PRELOAD(kt, bufb) do { \
    size_t _tok = ktok0 + (size_t)(kt) * 64 + krow; \
    uint32_t _dst = sb + AKV0 + (bufb) * AKVSZ + krow * AST + kp * 16; \
    const char* _s0 = (const char*)(kh + _tok * QKVN) + kp * 16; \
    const char* _s1 = (const char*)(vh + _tok * QKVN) + kp * 16; \
    CP_ASYNC16(_dst + 0,            _s0); \
    CP_ASYNC16(_dst + 16,           _s0 + 16); \
    CP_ASYNC16(_dst + 64*AST + 0,   _s1); \
    CP_ASYNC16(_dst + 64*AST + 16,  _s1 + 16); \
    if (tid < 64) CP_ASYNC4(sb + AMSK + (bufb)*256 + tid*4, maskf + b*SS + (kt)*64 + tid); \
} while (0)

    {
        int qrow = tid >> 1, qp = (tid & 1) * 4;
        const char* gq = (const char*)(qh + (qtok0 + qrow) * QKVN) + qp * 16;
        uint32_t d = sb + qrow * AST + qp * 16;
        #pragma unroll
        for (int i = 0; i < 4; i++)
            CP_ASYNC16(d + i*16, gq + i*16);
    }
    KV_PRELOAD(0, 0);
    CP_COMMIT();

    uint32_t qhf[4][4];
    float oacc[8][4];
    #pragma unroll
    for (int i = 0; i < 8; i++)
        #pragma unroll
        for (int e = 0; e < 4; e++) oacc[i][e] = 0.f;
    float m0 = -1e30f, m1 = -1e30f, l0 = 0.f, l1 = 0.f;

    const int nTiles = SS / 64;
    for (int t = 0; t < nTiles; t++) {
        int buf = t & 1;
        CP_WAIT(0);
        __syncthreads();
        if (t + 1 < nTiles) { KV_PRELOAD(t + 1, (t + 1) & 1); CP_COMMIT(); }

        if (t == 0) {
            #pragma unroll
            for (int kc = 0; kc < 4; kc++) {
                uint32_t off = (wid * 16 + aRow) * AST + kc * 32 + aHalf * 16;
                ldm_x4(qhf[kc], sb + off);
            }
        }

        uint32_t kvb = sb + AKV0 + buf * AKVSZ;
        float sacc[8][4];
        #pragma unroll
        for (int i = 0; i < 8; i++)
            #pragma unroll
            for (int e = 0; e < 4; e++) sacc[i][e] = 0.f;

        #pragma unroll
        for (int kc = 0; kc < 4; kc++) {
            uint32_t kf[4][4];
            #pragma unroll
            for (int nt4 = 0; nt4 < 4; nt4++) {
                uint32_t kb = kvb + (nt4 * 16 + bN) * AST + kc * 32 + bHalf * 16;
                ldm_x4(kf[nt4], kb);
            }
            #pragma unroll
            for (int nt4 = 0; nt4 < 4; nt4++) {
                mma_f16(sacc[nt4*2],   qhf[kc], kf[nt4]);
                mma_f16(sacc[nt4*2+1], qhf[kc], kf[nt4] + 2);
            }
        }

        const float* smk = (const float*)(smA + AMSK + buf * 256);
        float mx0 = -1e30f, mx1 = -1e30f;
        #pragma unroll
        for (int nt = 0; nt < 8; nt++) {
            float mk0 = smk[nt * 8 + (lane & 3) * 2];
            float mk1 = smk[nt * 8 + (lane & 3) * 2 + 1];
            if (mk0 == 0.f) { sacc[nt][0] = -1e30f; sacc[nt][2] = -1e30f; }
            if (mk1 == 0.f) { sacc[nt][1] = -1e30f; sacc[nt][3] = -1e30f; }
            mx0 = fmaxf(mx0, fmaxf(sacc[nt][0], sacc[nt][1]));
            mx1 = fmaxf(mx1, fmaxf(sacc[nt][2], sacc[nt][3]));
        }
        mx0 = fmaxf(mx0, __shfl_xor_sync(0xffffffffu, mx0, 1));
        mx0 = fmaxf(mx0, __shfl_xor_sync(0xffffffffu, mx0, 2));
        mx1 = fmaxf(mx1, __shfl_xor_sync(0xffffffffu, mx1, 1));
        mx1 = fmaxf(mx1, __shfl_xor_sync(0xffffffffu, mx1, 2));
        float mn0 = fmaxf(m0, mx0), mn1 = fmaxf(m1, mx1);
        float al0 = __expf(m0 - mn0), al1 = __expf(m1 - mn1);
        m0 = mn0; m1 = mn1;
        float ps0 = 0.f, ps1 = 0.f;
        #pragma unroll
        for (int nt = 0; nt < 8; nt++) {
            sacc[nt][0] = __expf(sacc[nt][0] - mn0);
            sacc[nt][1] = __expf(sacc[nt][1] - mn0);
            sacc[nt][2] = __expf(sacc[nt][2] - mn1);
            sacc[nt][3] = __expf(sacc[nt][3] - mn1);
            ps0 += sacc[nt][0] + sacc[nt][1];
            ps1 += sacc[nt][2] + sacc[nt][3];
        }
        l0 = l0 * al0 + ps0;
        l1 = l1 * al1 + ps1;
        #pragma unroll
        for (int nt = 0; nt < 8; nt++) {
            oacc[nt][0] *= al0; oacc[nt][1] *= al0;
            oacc[nt][2] *= al1; oacc[nt][3] *= al1;
        }

        #pragma unroll
        for (int kc2 = 0; kc2 < 4; kc2++) {
            uint32_t pf[4];
            pf[0] = packpair(sacc[2*kc2][0],   sacc[2*kc2][1]);
            pf[1] = packpair(sacc[2*kc2][2],   sacc[2*kc2][3]);
            pf[2] = packpair(sacc[2*kc2+1][0], sacc[2*kc2+1][1]);
            pf[3] = packpair(sacc[2*kc2+1][2], sacc[2*kc2+1][3]);
            uint32_t vf[4][4];
            #pragma unroll
            for (int nt4 = 0; nt4 < 4; nt4++) {
                uint32_t va = kvb + 64*AST + (kc2*16 + vKey)*AST + (nt4*16 + vCol)*2;
                ldm_x4_t(vf[nt4], va);
            }
            #pragma unroll
            for (int nt4 = 0; nt4 < 4; nt4++) {
                uint32_t b0[2] = {vf[nt4][0], vf[nt4][2]}, b1[2] = {vf[nt4][1], vf[nt4][3]};
                mma_f16(oacc[nt4*2],   pf, b0);
                mma_f16(oacc[nt4*2+1], pf, b1);
            }
        }
    }

    l0 += __shfl_xor_sync(0xffffffffu, l0, 1);
    l0 += __shfl_xor_sync(0xffffffffu, l0, 2);
    l1 += __shfl_xor_sync(0xffffffffu, l1, 1);
    l1 += __shfl_xor_sync(0xffffffffu, l1, 2);
    float inv0 = 1.f / l0, inv1 = 1.f / l1;
    size_t tok0 = qtok0 + wid * 16 + (lane >> 2);
    size_t tok1 = tok0 + 8;
    int cb = colbase + (lane & 3) * 2;
    #pragma unroll
    for (int nt = 0; nt < 8; nt++) {
        int col = cb + nt * 8;
        *reinterpret_cast<__half2*>(outh + tok0*DD + col) =
            __floats2half2_rn(oacc[nt][0] * inv0, oacc[nt][1] * inv0);
        *reinterpret_cast<__half2*>(outh + tok1*DD + col) =
            __floats2half2_rn(oacc[nt][2] * inv1, oacc[nt][3] * inv1);
    }
#undef KV_PRELOAD
}

// ---------------- pooling: deterministic two-stage ------------------------
__global__ void pool_partial(const float* __restrict__ h,
                             const float* __restrict__ maskf) {
    __shared__ float scnt[64];
    int b = blockIdx.x, chunk = blockIdx.y, tid = threadIdx.x;
    int s0 = chunk * 64;
    if (tid < 64) scnt[tid] = maskf[b * SS + s0 + tid];
    float a0 = 0.f, a1 = 0.f;
    for (int s = s0; s < s0 + 64; s++) {
        float np = maskf[b * SS + s];
        const float* hp = h + (size_t)(b * SS + s) * DD;
        a0 += hp[tid] * np;
        a1 += hp[tid + 256] * np;
    }
    g_pool[(size_t)(b * 16 + chunk) * DD + tid]       = a0;
    g_pool[(size_t)(b * 16 + chunk) * DD + tid + 256] = a1;
    __syncthreads();
    if (tid == 0) {
        float c = 0.f;
        #pragma unroll
        for (int i = 0; i < 64; i++) c += scnt[i];
        g_cnt[b * 16 + chunk] = c;
    }
}

__global__ void pool_final(const float* __restrict__ Wout,
                           const float* __restrict__ bout,
                           float* __restrict__ out) {
    __shared__ float red[40];
    int b = blockIdx.x, tid = threadIdx.x;
    float a0 = 0.f, a1 = 0.f, cnt = 0.f;
    #pragma unroll
    for (int c = 0; c < 16; c++) {
        a0 += g_pool[(size_t)(b * 16 + c) * DD + tid];
        a1 += g_pool[(size_t)(b * 16 + c) * DD + tid + 256];
        cnt += g_cnt[b * 16 + c];
    }
    float inv = 1.f / (cnt + 1e-8f);
    float p0 = a0 * inv, p1 = a1 * inv;
    for (int j = 0; j < OUTD; j++) {
        float p = p0 * Wout[tid * OUTD + j] + p1 * Wout[(tid + 256) * OUTD + j];
        float ssum = block_sum(p, red);
        if (tid == 0) out[b * OUTD + j] = ssum + bout[j];
    }
}

// ---------------- launch ---------------------------------------------------
extern "C" void kernel_launch(void* const* d_in, const int* in_sizes, int n_in,
                              void* d_out, int out_size) {
    const float* x     = (const float*)d_in[0];
    const float* Wproj = (const float*)d_in[1];
    const float* bproj = (const float*)d_in[2];
    const float* gp    = (const float*)d_in[3];
    const float* bp    = (const float*)d_in[4];
    const float* Wq    = (const float*)d_in[5];
    const float* Wk    = (const float*)d_in[6];
    const float* Wv    = (const float*)d_in[7];
    const float* Wo    = (const float*)d_in[8];
    const float* g1    = (const float*)d_in[9];
    const float* b1    = (const float*)d_in[10];
    const float* W1    = (const float*)d_in[11];
    const float* W2    = (const float*)d_in[12];
    const float* g2    = (const float*)d_in[13];
    const float* b2    = (const float*)d_in[14];
    const float* gf    = (const float*)d_in[15];
    const float* bf    = (const float*)d_in[16];
    const float* Wout  = (const float*)d_in[17];
    const float* bout  = (const float*)d_in[18];

    float *h, *mask;
    cudaGetSymbolAddress((void**)&h,    g_h);
    cudaGetSymbolAddress((void**)&mask, g_mask);
    __half *hh, *ao, *fh, *qkv;
    cudaGetSymbolAddress((void**)&hh,  g_hh);
    cudaGetSymbolAddress((void**)&ao,  g_ao);
    cudaGetSymbolAddress((void**)&fh,  g_fh);
    cudaGetSymbolAddress((void**)&qkv, g_qkv);
    __half *wqkv, *wo, *w1, *w2;
    cudaGetSymbolAddress((void**)&wqkv, g_wqkv);
    cudaGetSymbolAddress((void**)&wo,   g_wo);
    cudaGetSymbolAddress((void**)&w1,   g_w1);
    cudaGetSymbolAddress((void**)&w2,   g_w2);

    cudaFuncSetAttribute(gemm_mma<1>, cudaFuncAttributeMaxDynamicSharedMemorySize, GEMM_SMEM);
    cudaFuncSetAttribute(gemm_mma<2>, cudaFuncAttributeMaxDynamicSharedMemorySize, GEMM_SMEM);
    cudaFuncSetAttribute(gemm_mma<3>, cudaFuncAttributeMaxDynamicSharedMemorySize, GEMM_SMEM);
    cudaFuncSetAttribute(attn_mma,    cudaFuncAttributeMaxDynamicSharedMemorySize, ATT_SMEM);

    wprep_all<<<12288, dim3(32, 8)>>>(Wq, Wk, Wv, Wo, W1, W2);

    embed_kernel<<<NT, 256>>>(x, Wproj, bproj, h, mask);
    ln_kernel<<<NT/8, 256>>>(h, gp, bp, hh);

    dim3 gQKV(QKVN / 128, NT / 128);
    dim3 gO(DD / 128, NT / 128);
    dim3 gF1(FF / 128, NT / 128);
    dim3 gAttn(SS / 128, HH, BB);

    for (int l = 0; l < LL; l++) {
        size_t oqkv = (size_t)l * QKVN * DD;
        size_t od = (size_t)l * DD * DD, of1 = (size_t)l * FF * DD, of2 = (size_t)l * DD * FF;
        gemm_mma<2><<<gQKV, 256, GEMM_SMEM>>>(hh, wqkv + oqkv, nullptr, qkv, NT, QKVN, DD);
        attn_mma<<<gAttn, 256, ATT_SMEM>>>(qkv, mask, ao);
        gemm_mma<3><<<gO, 256, GEMM_SMEM>>>(ao, wo + od, h, nullptr, NT, DD, DD);
        ln_kernel<<<NT/8, 256>>>(h, g1 + l * DD, b1 + l * DD, hh);
        gemm_mma<1><<<gF1, 256, GEMM_SMEM>>>(hh, w1 + of1, nullptr, fh, NT, FF, DD);
        gemm_mma<3><<<gO, 256, GEMM_SMEM>>>(fh, w2 + of2, h, nullptr, NT, DD, FF);
        ln_kernel<<<NT/8, 256>>>(h, g2 + l * DD, b2 + l * DD, hh);
    }

    ln_kernel<<<NT/8, 256>>>(h, gf, bf, nullptr);
    pool_partial<<<dim3(BB, 16), 256>>>(h, mask);
    pool_final<<<BB, 256>>>(Wout, bout, (float*)d_out);
}

// round 17
// speedup vs baseline: 1.0628x; 1.0295x over previous
#include <cuda_runtime.h>
#include <cuda_fp16.h>
#include <math.h>
#include <stdint.h>

// Problem constants
#define BB 8
#define SS 1024
#define IN_DIM 3
#define DD 512
#define HH 8
#define FF 2048
#define LL 4
#define OUTD 6
#define DH 64
#define NT (BB*SS)   // 8192 tokens
#define QKVN 1536    // fused QKV output width

// ======================= PTX helpers (portable, sm_80+) ====================
__device__ __forceinline__ uint32_t smem_to_u32(const void* p) {
    uint32_t a;
    asm("{ .reg .u64 t; cvta.to.shared.u64 t, %1; cvt.u32.u64 %0, t; }" : "=r"(a) : "l"(p));
    return a;
}
#define CP_ASYNC16(dst, src) \
    asm volatile("cp.async.cg.shared.global [%0], [%1], 16;" :: "r"(dst), "l"(src))
#define CP_ASYNC4(dst, src) \
    asm volatile("cp.async.ca.shared.global [%0], [%1], 4;" :: "r"(dst), "l"(src))
#define CP_COMMIT() asm volatile("cp.async.commit_group;" ::: "memory")
#define CP_WAIT(n)  asm volatile("cp.async.wait_group %0;" :: "n"(n) : "memory")

__device__ __forceinline__ void ldm_x4(uint32_t* r, uint32_t addr) {
    asm volatile("ldmatrix.sync.aligned.m8n8.x4.shared.b16 {%0,%1,%2,%3}, [%4];"
        : "=r"(r[0]), "=r"(r[1]), "=r"(r[2]), "=r"(r[3]) : "r"(addr));
}
__device__ __forceinline__ void ldm_x4_t(uint32_t* r, uint32_t addr) {
    asm volatile("ldmatrix.sync.aligned.m8n8.x4.trans.shared.b16 {%0,%1,%2,%3}, [%4];"
        : "=r"(r[0]), "=r"(r[1]), "=r"(r[2]), "=r"(r[3]) : "r"(addr));
}
__device__ __forceinline__ void mma_f16(float* d, const uint32_t* a, const uint32_t* b) {
    asm volatile("mma.sync.aligned.m16n8k16.row.col.f32.f16.f16.f32 "
        "{%0,%1,%2,%3}, {%4,%5,%6,%7}, {%8,%9}, {%0,%1,%2,%3};"
        : "+f"(d[0]), "+f"(d[1]), "+f"(d[2]), "+f"(d[3])
        : "r"(a[0]), "r"(a[1]), "r"(a[2]), "r"(a[3]), "r"(b[0]), "r"(b[1]));
}
__device__ __forceinline__ float ex2(float x) {   // raw exp2 (softmax domain)
    float y;
    asm("ex2.approx.ftz.f32 %0, %1;" : "=f"(y) : "f"(x));
    return y;
}

// ---------------- scratch (device globals; no allocation allowed) ----------
__device__ float g_h  [NT*DD];
__device__ float g_mask[NT];
__device__ float g_pool[BB*16*DD];
__device__ float g_cnt[BB*16];
// fp16 activations
__device__ __half g_hh  [NT*DD];
__device__ __half g_ao  [NT*DD];
__device__ __half g_fh  [NT*FF];
__device__ __half g_qkv [NT*QKVN];
// fp16, transposed weights [N, K]  (Wq block pre-scaled by 0.125*log2e)
__device__ __half g_wqkv[LL*QKVN*DD];
__device__ __half g_wo[LL*DD*DD];
__device__ __half g_w1[LL*FF*DD];
__device__ __half g_w2[LL*DD*FF];

__device__ __forceinline__ uint32_t packpair(float a, float b) {
    __half2 t = __floats2half2_rn(a, b);
    return *reinterpret_cast<uint32_t*>(&t);
}
__device__ __forceinline__ float wred_sum(float v) {
    #pragma unroll
    for (int o = 16; o > 0; o >>= 1) v += __shfl_xor_sync(0xffffffffu, v, o);
    return v;
}
__device__ __forceinline__ float block_sum(float v, float* red) {
    int lane = threadIdx.x & 31, w = threadIdx.x >> 5;
    v = wred_sum(v);
    if (lane == 0) red[w] = v;
    __syncthreads();
    if (w == 0) {
        float r = (lane < (int)(blockDim.x >> 5)) ? red[lane] : 0.f;
        r = wred_sum(r);
        if (lane == 0) red[32] = r;
    }
    __syncthreads();
    return red[32];
}

// -------- single-launch weight prep: transpose + fp16, QKV packed ---------
// Wq is pre-scaled by 0.125*log2(e): QK scores land in the exp2 domain, so
// softmax uses raw ex2 (scale cancels in normalization).
__global__ void wprep_all(const float* __restrict__ Wq, const float* __restrict__ Wk,
                          const float* __restrict__ Wv, const float* __restrict__ Wo,
                          const float* __restrict__ W1, const float* __restrict__ W2) {
    __shared__ float tile[32][33];
    int gid = blockIdx.x;
    int l = gid / 3072, r = gid % 3072;
    const float* src; __half* dh;
    int K, N, n0, k0;
    float scale = 1.f;
    if (r < 1024) {
        int widx = r >> 8, t = r & 255;
        n0 = (t & 15) * 32; k0 = (t >> 4) * 32;
        K = DD; N = DD;
        size_t wo = (size_t)l * DD * DD;
        if (widx < 3) {
            const float* ws[3] = {Wq, Wk, Wv};
            src = ws[widx] + wo;
            dh = g_wqkv + (size_t)l * QKVN * DD + (size_t)widx * DD * DD;
            if (widx == 0) scale = 0.125f * 1.4426950408889634f;
        } else {
            src = Wo + wo; dh = g_wo + wo;
        }
    } else if (r < 2048) {
        int t = r - 1024;
        n0 = (t & 63) * 32; k0 = (t >> 6) * 32;
        K = DD; N = FF;
        size_t wo = (size_t)l * FF * DD;
        src = W1 + wo; dh = g_w1 + wo;
    } else {
        int t = r - 2048;
        n0 = (t & 15) * 32; k0 = (t >> 4) * 32;
        K = FF; N = DD;
        size_t wo = (size_t)l * DD * FF;
        src = W2 + wo; dh = g_w2 + wo;
    }
    int tx = threadIdx.x, ty = threadIdx.y;
    #pragma unroll
    for (int j = 0; j < 32; j += 8)
        tile[ty + j][tx] = src[(size_t)(k0 + ty + j) * N + n0 + tx];
    __syncthreads();
    #pragma unroll
    for (int j = 0; j < 32; j += 8) {
        size_t idx = (size_t)(n0 + ty + j) * K + k0 + tx;
        dh[idx] = __float2half(tile[tx][ty + j] * scale);
    }
}

// ------- fused embed + first LN: warp-per-token, grid NT/8 ----------------
__global__ __launch_bounds__(256)
void embed_ln_kernel(const float* __restrict__ x,
                     const float* __restrict__ Wp,
                     const float* __restrict__ bpj,
                     const float* __restrict__ g,
                     const float* __restrict__ bta,
                     float* __restrict__ h,
                     __half* __restrict__ oh,
                     float* __restrict__ maskf) {
    int w = threadIdx.x >> 5, lane = threadIdx.x & 31;
    size_t t = (size_t)blockIdx.x * 8 + w;
    int sPos = (int)(t & (SS - 1));
    const float* xt = x + t * IN_DIM;
    float x0 = xt[0], x1 = xt[1], x2 = xt[2];
    if (lane == 0)
        maskf[t] = ((fabsf(x0) + fabsf(x1) + fabsf(x2)) == 0.f) ? 0.f : 1.f;

    float v[16];
    float s = 0.f;
    #pragma unroll
    for (int i = 0; i < 4; i++) {
        int c = i * 128 + lane * 4;
        float4 w0 = *reinterpret_cast<const float4*>(Wp + c);
        float4 w1 = *reinterpret_cast<const float4*>(Wp + DD + c);
        float4 w2 = *reinterpret_cast<const float4*>(Wp + 2*DD + c);
        float4 bb = *reinterpret_cast<const float4*>(bpj + c);
        float vv[4];
        vv[0] = x0*w0.x + x1*w1.x + x2*w2.x + bb.x;
        vv[1] = x0*w0.y + x1*w1.y + x2*w2.y + bb.y;
        vv[2] = x0*w0.z + x1*w1.z + x2*w2.z + bb.z;
        vv[3] = x0*w0.w + x1*w1.w + x2*w2.w + bb.w;
        #pragma unroll
        for (int e = 0; e < 4; e++) {
            int d = c + e;
            float freq = expf(-(float)(d & ~1) * (9.210340371976184f / (float)DD));
            float ang = (float)sPos * freq;
            vv[e] += (d & 1) ? cosf(ang) : sinf(ang);
            v[i*4+e] = vv[e];
            s += vv[e];
        }
    }
    float mean = wred_sum(s) * (1.f / (float)DD);
    float vs = 0.f;
    #pragma unroll
    for (int i = 0; i < 16; i++) { v[i] -= mean; vs += v[i] * v[i]; }
    float rs = rsqrtf(wred_sum(vs) * (1.f / (float)DD) + 1e-5f);
    #pragma unroll
    for (int i = 0; i < 4; i++) {
        int c = i * 128 + lane * 4;
        float4 gg = *reinterpret_cast<const float4*>(g + c);
        float4 bb = *reinterpret_cast<const float4*>(bta + c);
        float y0 = v[i*4+0] * rs * gg.x + bb.x;
        float y1 = v[i*4+1] * rs * gg.y + bb.y;
        float y2 = v[i*4+2] * rs * gg.z + bb.z;
        float y3 = v[i*4+3] * rs * gg.w + bb.w;
        *reinterpret_cast<float4*>(h + t*DD + c) = make_float4(y0, y1, y2, y3);
        *reinterpret_cast<__half2*>(oh + t*DD + c)     = __floats2half2_rn(y0, y1);
        *reinterpret_cast<__half2*>(oh + t*DD + c + 2) = __floats2half2_rn(y2, y3);
    }
}

// ------- warp-per-row LN; emits fp16 unless oh == nullptr -----------------
__global__ __launch_bounds__(256)
void ln_kernel(float* __restrict__ h,
               const float* __restrict__ g,
               const float* __restrict__ bta,
               __half* __restrict__ oh) {
    int w = threadIdx.x >> 5, lane = threadIdx.x & 31;
    size_t t = (size_t)blockIdx.x * 8 + w;
    float* hp = h + t * DD;
    float v[16];
    float s = 0.f;
    #pragma unroll
    for (int i = 0; i < 4; i++) {
        int c = i * 128 + lane * 4;
        float4 a = *reinterpret_cast<const float4*>(hp + c);
        v[i*4+0]=a.x; v[i*4+1]=a.y; v[i*4+2]=a.z; v[i*4+3]=a.w;
        s += a.x + a.y + a.z + a.w;
    }
    float mean = wred_sum(s) * (1.f / (float)DD);
    float vs = 0.f;
    #pragma unroll
    for (int i = 0; i < 16; i++) { v[i] -= mean; vs += v[i] * v[i]; }
    float rs = rsqrtf(wred_sum(vs) * (1.f / (float)DD) + 1e-5f);
    #pragma unroll
    for (int i = 0; i < 4; i++) {
        int c = i * 128 + lane * 4;
        float4 gg = *reinterpret_cast<const float4*>(g + c);
        float4 bb = *reinterpret_cast<const float4*>(bta + c);
        float y0 = v[i*4+0] * rs * gg.x + bb.x;
        float y1 = v[i*4+1] * rs * gg.y + bb.y;
        float y2 = v[i*4+2] * rs * gg.z + bb.z;
        float y3 = v[i*4+3] * rs * gg.w + bb.w;
        *reinterpret_cast<float4*>(hp + c) = make_float4(y0, y1, y2, y3);
        if (oh) {
            *reinterpret_cast<__half2*>(oh + t*DD + c)     = __floats2half2_rn(y0, y1);
            *reinterpret_cast<__half2*>(oh + t*DD + c + 2) = __floats2half2_rn(y2, y3);
        }
    }
}

// =================== warp-MMA fp16 GEMM (single product) ===================
// 128x128 CTA, 8 warps of 32x64, BK=32, 3-stage pipeline, 1 barrier/chunk.
// EPI 0: fp32 C.  EPI 1: silu -> fp16.  EPI 2: fp16.  EPI 3: fp32 C += acc.
#define SMEM_STRIDE 80
#define MAT_BYTES   10240
#define GEMM_SMEM   (3 * 2 * MAT_BYTES)   // 61440

template <int EPI>
__global__ __launch_bounds__(256, 2)
void gemm_mma(const __half* __restrict__ A, const __half* __restrict__ B,
              float* __restrict__ C, __half* __restrict__ Ch,
              int M, int N, int K) {
    extern __shared__ char smem[];
    const int tid = threadIdx.x, lane = tid & 31, wid = tid >> 5;
    const int mBase = blockIdx.y * 128, nBase = blockIdx.x * 128;
    const int wm = wid >> 1, wn = wid & 1;
    uint32_t sbase = smem_to_u32(smem);

    float acc[2][8][4];
    #pragma unroll
    for (int i = 0; i < 2; i++)
        #pragma unroll
        for (int j = 0; j < 8; j++)
            #pragma unroll
            for (int e = 0; e < 4; e++) acc[i][j][e] = 0.f;

    const int nChunks = K >> 5;
    int idx0 = tid << 1;
    int r0 = idx0 >> 2, p0 = idx0 & 3;
    int p1 = p0 + 1;

    int aRow  = lane & 15;
    int aHalf = lane >> 4;
    int bN    = (lane & 7) | ((lane & 16) >> 1);
    int bHalf = (lane >> 3) & 1;

    const __half* gmat[2] = {A, B};
    int rbase[2] = {mBase, nBase};

#define PRELOAD(c, buf) do { \
    uint32_t _dst = sbase + (buf) * (2 * MAT_BYTES); \
    int _kc = (c) << 5; \
    _Pragma("unroll") \
    for (int _m = 0; _m < 2; _m++) { \
        const char* _g = (const char*)(gmat[_m] + (size_t)(rbase[_m] + r0) * K + _kc); \
        uint32_t _d = _dst + _m * MAT_BYTES + r0 * SMEM_STRIDE; \
        CP_ASYNC16(_d + p0 * 16, _g + p0 * 16); \
        CP_ASYNC16(_d + p1 * 16, _g + p1 * 16); \
    } \
} while (0)

    PRELOAD(0, 0); CP_COMMIT();
    PRELOAD(1, 1); CP_COMMIT();

    int buf = 0;
    for (int c = 0; c < nChunks; c++) {
        if (c + 1 < nChunks) CP_WAIT(1); else CP_WAIT(0);
        __syncthreads();
        if (c + 2 < nChunks) {
            int nb = buf + 2; if (nb >= 3) nb -= 3;
            PRELOAD(c + 2, nb); CP_COMMIT();
        }

        uint32_t bufb  = sbase + buf * (2 * MAT_BYTES);
        uint32_t aBase = bufb + (wm * 32) * SMEM_STRIDE;
        uint32_t bBase = bufb + MAT_BYTES + (wn * 64) * SMEM_STRIDE;

        #pragma unroll
        for (int ks = 0; ks < 2; ks++) {
            int koff  = ks * 32 + aHalf * 16;
            int koffb = ks * 32 + bHalf * 16;
            uint32_t af[2][4], bf[4][4];
            #pragma unroll
            for (int mi = 0; mi < 2; mi++)
                ldm_x4(af[mi], aBase + (mi * 16 + aRow) * SMEM_STRIDE + koff);
            #pragma unroll
            for (int g = 0; g < 4; g++)
                ldm_x4(bf[g], bBase + (g * 16 + bN) * SMEM_STRIDE + koffb);

            #pragma unroll
            for (int mi = 0; mi < 2; mi++)
                #pragma unroll
                for (int g = 0; g < 4; g++) {
                    mma_f16(acc[mi][g*2],   af[mi], bf[g]);
                    mma_f16(acc[mi][g*2+1], af[mi], bf[g] + 2);
                }
        }
        buf++; if (buf >= 3) buf = 0;
    }

    int rowb = mBase + wm * 32 + (lane >> 2);
    int colb = nBase + wn * 64 + (lane & 3) * 2;
    #pragma unroll
    for (int mi = 0; mi < 2; mi++) {
        #pragma unroll
        for (int ns = 0; ns < 8; ns++) {
            int row = rowb + mi * 16;
            int col = colb + ns * 8;
            float c0 = acc[mi][ns][0], c1 = acc[mi][ns][1];
            float c2 = acc[mi][ns][2], c3 = acc[mi][ns][3];
            if (EPI == 0) {
                *reinterpret_cast<float2*>(C + (size_t)row * N + col)       = make_float2(c0, c1);
                *reinterpret_cast<float2*>(C + (size_t)(row + 8) * N + col) = make_float2(c2, c3);
            } else if (EPI == 3) {
                float2 o0 = *reinterpret_cast<float2*>(C + (size_t)row * N + col);
                float2 o1 = *reinterpret_cast<float2*>(C + (size_t)(row + 8) * N + col);
                *reinterpret_cast<float2*>(C + (size_t)row * N + col)       = make_float2(o0.x + c0, o0.y + c1);
                *reinterpret_cast<float2*>(C + (size_t)(row + 8) * N + col) = make_float2(o1.x + c2, o1.y + c3);
            } else {
                if (EPI == 1) {
                    c0 = c0 / (1.f + __expf(-c0)); c1 = c1 / (1.f + __expf(-c1));
                    c2 = c2 / (1.f + __expf(-c2)); c3 = c3 / (1.f + __expf(-c3));
                }
                *reinterpret_cast<__half2*>(Ch + (size_t)row * N + col)       = __floats2half2_rn(c0, c1);
                *reinterpret_cast<__half2*>(Ch + (size_t)(row + 8) * N + col) = __floats2half2_rn(c2, c3);
            }
        }
    }
#undef PRELOAD
}

// =================== tensor-core flash attention (fp16) ====================
// BQ=128 per CTA (256 threads, 8 warps x 16 q-rows). Scores arrive in the
// exp2 domain (Wq pre-scaled by 0.125*log2e): softmax uses raw ex2.
// Single-product QK and PV; 2-stage KV pipeline, one barrier per tile.
#define AST   144
#define AQBYTES (128*AST)                // 18432
#define AKV0  AQBYTES
#define AKVSZ (2*64*AST)                 // 18432 (Kh + Vh)
#define AMSK  (AKV0 + 2*AKVSZ)           // 55296
#define ATT_SMEM (AMSK + 2*256 + 256)

__global__ __launch_bounds__(256)
void attn_mma(const __half* __restrict__ qkv,
              const float* __restrict__ maskf,
              __half* __restrict__ outh) {
    extern __shared__ char smA[];
    uint32_t sb = smem_to_u32(smA);
    const int tid = threadIdx.x, lane = tid & 31, wid = tid >> 5;
    const int qt = blockIdx.x, hd = blockIdx.y, b = blockIdx.z;
    const size_t qtok0 = (size_t)b * SS + qt * 128;
    const size_t ktok0 = (size_t)b * SS;
    const int colbase = hd * DH;

    const __half* qh = qkv + colbase;
    const __half* kh = qkv + DD + colbase;
    const __half* vh = qkv + 2*DD + colbase;

    const int aRow = lane & 15, aHalf = lane >> 4;
    const int bN = (lane & 7) | ((lane & 16) >> 1), bHalf = (lane >> 3) & 1;
    const int vKey = (lane & 7) + ((lane >> 4) << 3), vCol = lane & 8;

    const int krow = tid >> 2, kp = (tid & 3) * 2;

#define KV_PRELOAD(kt, bufb) do { \
    size_t _tok = ktok0 + (size_t)(kt) * 64 + krow; \
    uint32_t _dst = sb + AKV0 + (bufb) * AKVSZ + krow * AST + kp * 16; \
    const char* _s0 = (const char*)(kh + _tok * QKVN) + kp * 16; \
    const char* _s1 = (const char*)(vh + _tok * QKVN) + kp * 16; \
    CP_ASYNC16(_dst + 0,            _s0); \
    CP_ASYNC16(_dst + 16,           _s0 + 16); \
    CP_ASYNC16(_dst + 64*AST + 0,   _s1); \
    CP_ASYNC16(_dst + 64*AST + 16,  _s1 + 16); \
    if (tid < 64) CP_ASYNC4(sb + AMSK + (bufb)*256 + tid*4, maskf + b*SS + (kt)*64 + tid); \
} while (0)

    {
        int qrow = tid >> 1, qp = (tid & 1) * 4;
        const char* gq = (const char*)(qh + (qtok0 + qrow) * QKVN) + qp * 16;
        uint32_t d = sb + qrow * AST + qp * 16;
        #pragma unroll
        for (int i = 0; i < 4; i++)
            CP_ASYNC16(d + i*16, gq + i*16);
    }
    KV_PRELOAD(0, 0);
    CP_COMMIT();

    uint32_t qhf[4][4];
    float oacc[8][4];
    #pragma unroll
    for (int i = 0; i < 8; i++)
        #pragma unroll
        for (int e = 0; e < 4; e++) oacc[i][e] = 0.f;
    float m0 = -1e30f, m1 = -1e30f, l0 = 0.f, l1 = 0.f;

    const int nTiles = SS / 64;
    for (int t = 0; t < nTiles; t++) {
        int buf = t & 1;
        CP_WAIT(0);
        __syncthreads();
        if (t + 1 < nTiles) { KV_PRELOAD(t + 1, (t + 1) & 1); CP_COMMIT(); }

        if (t == 0) {
            #pragma unroll
            for (int kc = 0; kc < 4; kc++) {
                uint32_t off = (wid * 16 + aRow) * AST + kc * 32 + aHalf * 16;
                ldm_x4(qhf[kc], sb + off);
            }
        }

        uint32_t kvb = sb + AKV0 + buf * AKVSZ;
        float sacc[8][4];
        #pragma unroll
        for (int i = 0; i < 8; i++)
            #pragma unroll
            for (int e = 0; e < 4; e++) sacc[i][e] = 0.f;

        #pragma unroll
        for (int kc = 0; kc < 4; kc++) {
            uint32_t kf[4][4];
            #pragma unroll
            for (int nt4 = 0; nt4 < 4; nt4++) {
                uint32_t kb = kvb + (nt4 * 16 + bN) * AST + kc * 32 + bHalf * 16;
                ldm_x4(kf[nt4], kb);
            }
            #pragma unroll
            for (int nt4 = 0; nt4 < 4; nt4++) {
                mma_f16(sacc[nt4*2],   qhf[kc], kf[nt4]);
                mma_f16(sacc[nt4*2+1], qhf[kc], kf[nt4] + 2);
            }
        }

        const float* smk = (const float*)(smA + AMSK + buf * 256);
        float mx0 = -1e30f, mx1 = -1e30f;
        #pragma unroll
        for (int nt = 0; nt < 8; nt++) {
            float mk0 = smk[nt * 8 + (lane & 3) * 2];
            float mk1 = smk[nt * 8 + (lane & 3) * 2 + 1];
            if (mk0 == 0.f) { sacc[nt][0] = -1e30f; sacc[nt][2] = -1e30f; }
            if (mk1 == 0.f) { sacc[nt][1] = -1e30f; sacc[nt][3] = -1e30f; }
            mx0 = fmaxf(mx0, fmaxf(sacc[nt][0], sacc[nt][1]));
            mx1 = fmaxf(mx1, fmaxf(sacc[nt][2], sacc[nt][3]));
        }
        mx0 = fmaxf(mx0, __shfl_xor_sync(0xffffffffu, mx0, 1));
        mx0 = fmaxf(mx0, __shfl_xor_sync(0xffffffffu, mx0, 2));
        mx1 = fmaxf(mx1, __shfl_xor_sync(0xffffffffu, mx1, 1));
        mx1 = fmaxf(mx1, __shfl_xor_sync(0xffffffffu, mx1, 2));
        float mn0 = fmaxf(m0, mx0), mn1 = fmaxf(m1, mx1);
        float al0 = ex2(m0 - mn0), al1 = ex2(m1 - mn1);
        m0 = mn0; m1 = mn1;
        float ps0 = 0.f, ps1 = 0.f;
        #pragma unroll
        for (int nt = 0; nt < 8; nt++) {
            sacc[nt][0] = ex2(sacc[nt][0] - mn0);
            sacc[nt][1] = ex2(sacc[nt][1] - mn0);
            sacc[nt][2] = ex2(sacc[nt][2] - mn1);
            sacc[nt][3] = ex2(sacc[nt][3] - mn1);
            ps0 += sacc[nt][0] + sacc[nt][1];
            ps1 += sacc[nt][2] + sacc[nt][3];
        }
        l0 = l0 * al0 + ps0;
        l1 = l1 * al1 + ps1;
        #pragma unroll
        for (int nt = 0; nt < 8; nt++) {
            oacc[nt][0] *= al0; oacc[nt][1] *= al0;
            oacc[nt][2] *= al1; oacc[nt][3] *= al1;
        }

        #pragma unroll
        for (int kc2 = 0; kc2 < 4; kc2++) {
            uint32_t pf[4];
            pf[0] = packpair(sacc[2*kc2][0],   sacc[2*kc2][1]);
            pf[1] = packpair(sacc[2*kc2][2],   sacc[2*kc2][3]);
            pf[2] = packpair(sacc[2*kc2+1][0], sacc[2*kc2+1][1]);
            pf[3] = packpair(sacc[2*kc2+1][2], sacc[2*kc2+1][3]);
            uint32_t vf[4][4];
            #pragma unroll
            for (int nt4 = 0; nt4 < 4; nt4++) {
                uint32_t va = kvb + 64*AST + (kc2*16 + vKey)*AST + (nt4*16 + vCol)*2;
                ldm_x4_t(vf[nt4], va);
            }
            #pragma unroll
            for (int nt4 = 0; nt4 < 4; nt4++) {
                uint32_t b0[2] = {vf[nt4][0], vf[nt4][2]}, b1[2] = {vf[nt4][1], vf[nt4][3]};
                mma_f16(oacc[nt4*2],   pf, b0);
                mma_f16(oacc[nt4*2+1], pf, b1);
            }
        }
    }

    l0 += __shfl_xor_sync(0xffffffffu, l0, 1);
    l0 += __shfl_xor_sync(0xffffffffu, l0, 2);
    l1 += __shfl_xor_sync(0xffffffffu, l1, 1);
    l1 += __shfl_xor_sync(0xffffffffu, l1, 2);
    float inv0 = 1.f / l0, inv1 = 1.f / l1;
    size_t tok0 = qtok0 + wid * 16 + (lane >> 2);
    size_t tok1 = tok0 + 8;
    int cb = colbase + (lane & 3) * 2;
    #pragma unroll
    for (int nt = 0; nt < 8; nt++) {
        int col = cb + nt * 8;
        *reinterpret_cast<__half2*>(outh + tok0*DD + col) =
            __floats2half2_rn(oacc[nt][0] * inv0, oacc[nt][1] * inv0);
        *reinterpret_cast<__half2*>(outh + tok1*DD + col) =
            __floats2half2_rn(oacc[nt][2] * inv1, oacc[nt][3] * inv1);
    }
#undef KV_PRELOAD
}

// ---------------- pooling: deterministic two-stage ------------------------
__global__ void pool_partial(const float* __restrict__ h,
                             const float* __restrict__ maskf) {
    __shared__ float scnt[64];
    int b = blockIdx.x, chunk = blockIdx.y, tid = threadIdx.x;
    int s0 = chunk * 64;
    if (tid < 64) scnt[tid] = maskf[b * SS + s0 + tid];
    float a0 = 0.f, a1 = 0.f;
    for (int s = s0; s < s0 + 64; s++) {
        float np = maskf[b * SS + s];
        const float* hp = h + (size_t)(b * SS + s) * DD;
        a0 += hp[tid] * np;
        a1 += hp[tid + 256] * np;
    }
    g_pool[(size_t)(b * 16 + chunk) * DD + tid]       = a0;
    g_pool[(size_t)(b * 16 + chunk) * DD + tid + 256] = a1;
    __syncthreads();
    if (tid == 0) {
        float c = 0.f;
        #pragma unroll
        for (int i = 0; i < 64; i++) c += scnt[i];
        g_cnt[b * 16 + chunk] = c;
    }
}

__global__ void pool_final(const float* __restrict__ Wout,
                           const float* __restrict__ bout,
                           float* __restrict__ out) {
    __shared__ float red[40];
    int b = blockIdx.x, tid = threadIdx.x;
    float a0 = 0.f, a1 = 0.f, cnt = 0.f;
    #pragma unroll
    for (int c = 0; c < 16; c++) {
        a0 += g_pool[(size_t)(b * 16 + c) * DD + tid];
        a1 += g_pool[(size_t)(b * 16 + c) * DD + tid + 256];
        cnt += g_cnt[b * 16 + c];
    }
    float inv = 1.f / (cnt + 1e-8f);
    float p0 = a0 * inv, p1 = a1 * inv;
    for (int j = 0; j < OUTD; j++) {
        float p = p0 * Wout[tid * OUTD + j] + p1 * Wout[(tid + 256) * OUTD + j];
        float ssum = block_sum(p, red);
        if (tid == 0) out[b * OUTD + j] = ssum + bout[j];
    }
}

// ---------------- launch ---------------------------------------------------
extern "C" void kernel_launch(void* const* d_in, const int* in_sizes, int n_in,
                              void* d_out, int out_size) {
    const float* x     = (const float*)d_in[0];
    const float* Wproj = (const float*)d_in[1];
    const float* bproj = (const float*)d_in[2];
    const float* gp    = (const float*)d_in[3];
    const float* bp    = (const float*)d_in[4];
    const float* Wq    = (const float*)d_in[5];
    const float* Wk    = (const float*)d_in[6];
    const float* Wv    = (const float*)d_in[7];
    const float* Wo    = (const float*)d_in[8];
    const float* g1    = (const float*)d_in[9];
    const float* b1    = (const float*)d_in[10];
    const float* W1    = (const float*)d_in[11];
    const float* W2    = (const float*)d_in[12];
    const float* g2    = (const float*)d_in[13];
    const float* b2    = (const float*)d_in[14];
    const float* gf    = (const float*)d_in[15];
    const float* bf    = (const float*)d_in[16];
    const float* Wout  = (const float*)d_in[17];
    const float* bout  = (const float*)d_in[18];

    float *h, *mask;
    cudaGetSymbolAddress((void**)&h,    g_h);
    cudaGetSymbolAddress((void**)&mask, g_mask);
    __half *hh, *ao, *fh, *qkv;
    cudaGetSymbolAddress((void**)&hh,  g_hh);
    cudaGetSymbolAddress((void**)&ao,  g_ao);
    cudaGetSymbolAddress((void**)&fh,  g_fh);
    cudaGetSymbolAddress((void**)&qkv, g_qkv);
    __half *wqkv, *wo, *w1, *w2;
    cudaGetSymbolAddress((void**)&wqkv, g_wqkv);
    cudaGetSymbolAddress((void**)&wo,   g_wo);
    cudaGetSymbolAddress((void**)&w1,   g_w1);
    cudaGetSymbolAddress((void**)&w2,   g_w2);

    cudaFuncSetAttribute(gemm_mma<1>, cudaFuncAttributeMaxDynamicSharedMemorySize, GEMM_SMEM);
    cudaFuncSetAttribute(gemm_mma<2>, cudaFuncAttributeMaxDynamicSharedMemorySize, GEMM_SMEM);
    cudaFuncSetAttribute(gemm_mma<3>, cudaFuncAttributeMaxDynamicSharedMemorySize, GEMM_SMEM);
    cudaFuncSetAttribute(attn_mma,    cudaFuncAttributeMaxDynamicSharedMemorySize, ATT_SMEM);

    wprep_all<<<12288, dim3(32, 8)>>>(Wq, Wk, Wv, Wo, W1, W2);

    embed_ln_kernel<<<NT/8, 256>>>(x, Wproj, bproj, gp, bp, h, hh, mask);

    dim3 gQKV(QKVN / 128, NT / 128);
    dim3 gO(DD / 128, NT / 128);
    dim3 gF1(FF / 128, NT / 128);
    dim3 gAttn(SS / 128, HH, BB);

    for (int l = 0; l < LL; l++) {
        size_t oqkv = (size_t)l * QKVN * DD;
        size_t od = (size_t)l * DD * DD, of1 = (size_t)l * FF * DD, of2 = (size_t)l * DD * FF;
        gemm_mma<2><<<gQKV, 256, GEMM_SMEM>>>(hh, wqkv + oqkv, nullptr, qkv, NT, QKVN, DD);
        attn_mma<<<gAttn, 256, ATT_SMEM>>>(qkv, mask, ao);
        gemm_mma<3><<<gO, 256, GEMM_SMEM>>>(ao, wo + od, h, nullptr, NT, DD, DD);
        ln_kernel<<<NT/8, 256>>>(h, g1 + l * DD, b1 + l * DD, hh);
        gemm_mma<1><<<gF1, 256, GEMM_SMEM>>>(hh, w1 + of1, nullptr, fh, NT, FF, DD);
        gemm_mma<3><<<gO, 256, GEMM_SMEM>>>(fh, w2 + of2, h, nullptr, NT, DD, FF);
        ln_kernel<<<NT/8, 256>>>(h, g2 + l * DD, b2 + l * DD, hh);
    }

    ln_kernel<<<NT/8, 256>>>(h, gf, bf, nullptr);
    pool_partial<<<dim3(BB, 16), 256>>>(h, mask);
    pool_final<<<BB, 256>>>(Wout, bout, (float*)d_out);
}